// round 14
// baseline (speedup 1.0000x reference)
#include <cuda_runtime.h>
#include <cuda_fp16.h>
#include <cstdint>

#define N_NODES 200000
#define N_EDGES 400000
#define D 128
#define NLAYER 5
#define AVC 100
#define BVC 10
#define BN_EPS 1e-5f
#define ND ((size_t)N_NODES * D)

// ---------------- scratch (static device globals; no allocation) ----------------
__device__ __half g_hlh[ND];                    // linear output (fp16; gather-only consumer)
__device__ float g_outL[NLAYER * ND];           // per-layer aggregated output (pre-BN)
__device__ float g_h0[ND];                      // encoder output (layer-0 input)
__device__ float g_deg[N_NODES];
__device__ float g_enorm[N_EDGES];              // norm per CSR slot
__device__ int   g_eattr[N_EDGES];              // packed 3x4-bit bond attrs per CSR slot
__device__ int   g_indeg[N_NODES];
__device__ int   g_off[N_NODES];                // CSR offsets (exclusive scan)
__device__ int   g_cursor[N_NODES];
__device__ int   g_bsum[1024];
__device__ int   g_src[N_EDGES];                // source node per CSR slot
__device__ float g_stats[2 * D];                // sum, sumsq
__device__ float g_bnL[NLAYER * 2 * D];         // per-layer scale, shift
// pre-converted W (fp16, k-pair packed): [layer][chunk(8)][n(128)][8 words]
__device__ __align__(16) uint32_t g_wsplit[(size_t)NLAYER * 8 * 128 * 8];

// ---------------- helpers ----------------
__device__ __forceinline__ void mma_f16(float* d, const uint32_t* a, const uint32_t* b) {
    asm volatile(
        "mma.sync.aligned.m16n8k16.row.col.f32.f16.f16.f32 "
        "{%0,%1,%2,%3}, {%4,%5,%6,%7}, {%8,%9}, {%0,%1,%2,%3};\n"
        : "+f"(d[0]), "+f"(d[1]), "+f"(d[2]), "+f"(d[3])
        : "r"(a[0]), "r"(a[1]), "r"(a[2]), "r"(a[3]), "r"(b[0]), "r"(b[1]));
}

__device__ __forceinline__ void cp_async16(uint32_t smem_addr, const void* gptr) {
    asm volatile("cp.async.ca.shared.global [%0], [%1], 16;"
                 :: "r"(smem_addr), "l"(gptr));
}

// ---------------- W fp16 precompute (all layers, once) ----------------
__global__ void w_split_kernel(const float* __restrict__ W) {
    int idx = blockIdx.x * blockDim.x + threadIdx.x;   // over NLAYER*128*64
    if (idx >= NLAYER * 128 * 64) return;
    int l = idx / 8192;
    int rem = idx - l * 8192;
    int n = rem >> 6;
    int kp = rem & 63;                 // k-pair index
    int k = kp * 2;
    float a = W[(size_t)l * 16384 + n * 128 + k];
    float b = W[(size_t)l * 16384 + n * 128 + k + 1];
    __half2 h = __floats2half2_rn(a, b);
    size_t dst = ((size_t)(l * 8 + (k >> 4)) * 128 + n) * 8 + (kp & 7);
    g_wsplit[dst] = *(uint32_t*)&h;
}

// ---------------- setup: degrees + CSR ----------------
__global__ void init_kernel() {
    int stride = gridDim.x * blockDim.x;
    for (int i = blockIdx.x * blockDim.x + threadIdx.x; i < N_NODES; i += stride) {
        g_deg[i] = 1.f;
        g_indeg[i] = 0;
    }
}

__global__ void deg_acc_kernel(const int* __restrict__ row) {
    for (int e = blockIdx.x * blockDim.x + threadIdx.x; e < N_EDGES;
         e += gridDim.x * blockDim.x)
        atomicAdd(&g_deg[row[e]], 1.f);
}

__global__ void indeg_acc_kernel(const int* __restrict__ col) {
    for (int e = blockIdx.x * blockDim.x + threadIdx.x; e < N_EDGES;
         e += gridDim.x * blockDim.x)
        atomicAdd(&g_indeg[col[e]], 1);
}

__global__ void scan1_kernel() {
    __shared__ int sh[256];
    int tid = threadIdx.x;
    int i = blockIdx.x * 256 + tid;
    int v = (i < N_NODES) ? g_indeg[i] : 0;
    sh[tid] = v;
    __syncthreads();
#pragma unroll
    for (int ofs = 1; ofs < 256; ofs <<= 1) {
        int t = (tid >= ofs) ? sh[tid - ofs] : 0;
        __syncthreads();
        sh[tid] += t;
        __syncthreads();
    }
    if (i < N_NODES) g_off[i] = sh[tid] - v;  // exclusive
    if (tid == 255) g_bsum[blockIdx.x] = sh[255];
}

__global__ void scan2_kernel(int nblk) {   // single block of 1024
    __shared__ int sh[1024];
    int tid = threadIdx.x;
    int v = (tid < nblk) ? g_bsum[tid] : 0;
    sh[tid] = v;
    __syncthreads();
#pragma unroll
    for (int ofs = 1; ofs < 1024; ofs <<= 1) {
        int t = (tid >= ofs) ? sh[tid - ofs] : 0;
        __syncthreads();
        sh[tid] += t;
        __syncthreads();
    }
    if (tid < nblk) g_bsum[tid] = sh[tid] - v;  // exclusive
}

__global__ void scan3_kernel() {
    int i = blockIdx.x * 256 + threadIdx.x;
    if (i < N_NODES) {
        int o = g_off[i] + g_bsum[blockIdx.x];
        g_off[i] = o;
        g_cursor[i] = o;
    }
}

// fill CSR: src node, norm, and packed bond attrs per slot
__global__ void fill_kernel(const int* __restrict__ row, const int* __restrict__ col,
                            const int* __restrict__ ea) {
    for (int e = blockIdx.x * blockDim.x + threadIdx.x; e < N_EDGES;
         e += gridDim.x * blockDim.x) {
        int r = row[e], c = col[e];
        int pos = atomicAdd(&g_cursor[c], 1);
        g_src[pos] = r;
        g_enorm[pos] = rsqrtf(g_deg[r]) * rsqrtf(g_deg[c]);
        g_eattr[pos] = ea[e * 3] | (ea[e * 3 + 1] << 4) | (ea[e * 3 + 2] << 8);
    }
}

// ---------------- atom encoder ----------------
__global__ void encode_atoms_kernel(const int* __restrict__ x,
                                    const float* __restrict__ at,
                                    float* __restrict__ total) {
    int n = blockIdx.x * 4 + (threadIdx.x >> 5);
    if (n >= N_NODES) return;
    int d4 = (threadIdx.x & 31) * 4;
    float4 s = make_float4(0.f, 0.f, 0.f, 0.f);
#pragma unroll
    for (int c = 0; c < 9; c++) {
        int idx = __ldg(&x[n * 9 + c]);
        float4 v = *(const float4*)&at[((size_t)c * AVC + idx) * D + d4];
        s.x += v.x; s.y += v.y; s.z += v.z; s.w += v.w;
    }
    *(float4*)&g_h0[(size_t)n * D + d4] = s;
    *(float4*)&total[(size_t)n * D + d4] = s;
}

// ---------------- GEMM (fp16 MMA m16n8k16, fp32 accum, cp.async B) ----------------
// layer==0: A = g_h0 raw. layer>0: A = relu(bn(g_outL[layer-1])) on load (fp16-rounded).
// Writes g_hlh (fp16). Block 0 zeroes g_stats for the following gather.
__global__ __launch_bounds__(256, 2)
void gemm_tc_kernel(int layer, const float* __restrict__ bias) {
    __shared__ __align__(16) uint32_t shA[128 * 12];  // [row][8 k-pair words], stride 12
    __shared__ __align__(16) uint32_t shB[128 * 12];  // [n][8 k-pair words], stride 12

    const float* A = (layer == 0) ? g_h0 : (g_outL + (size_t)(layer - 1) * ND);
    const float* bn = g_bnL + (size_t)(layer > 0 ? layer - 1 : 0) * 2 * D;
    const int bn_mode = (layer > 0);
    const uint4* wbase = (const uint4*)&g_wsplit[(size_t)layer * 8 * 128 * 8];

    const int tid = threadIdx.x;
    if (blockIdx.x == 0 && tid < 2 * D) g_stats[tid] = 0.f;

    const int m0 = blockIdx.x * 128;
    const int lane = tid & 31, grp = lane >> 2, tig = lane & 3;
    const int wid = tid >> 5;
    const int wm = (wid & 1) * 64;
    const int wn = (wid >> 1) * 32;

    const int sr0 = tid >> 2,         sc0 = (tid & 3) * 4;
    const int sr1 = (tid + 256) >> 2, sc1 = ((tid + 256) & 3) * 4;

    const uint32_t bdst = (uint32_t)__cvta_generic_to_shared(
        &shB[(tid >> 1) * 12 + (tid & 1) * 4]);

    float acc[4][4][4];
#pragma unroll
    for (int i = 0; i < 4; i++)
#pragma unroll
        for (int j = 0; j < 4; j++)
#pragma unroll
            for (int k = 0; k < 4; k++) acc[i][j][k] = 0.f;

    const float4 z4 = make_float4(0.f, 0.f, 0.f, 0.f);
    float4 ra[2];
    {
        int m = m0 + sr0;
        ra[0] = (m < N_NODES) ? *(const float4*)&A[(size_t)m * D + sc0] : z4;
        m = m0 + sr1;
        ra[1] = (m < N_NODES) ? *(const float4*)&A[(size_t)m * D + sc1] : z4;
    }

    for (int k0 = 0; k0 < 128; k0 += 16) {
        cp_async16(bdst, wbase + (size_t)(k0 >> 4) * 256 + tid);
        asm volatile("cp.async.commit_group;");

#pragma unroll
        for (int it = 0; it < 2; it++) {
            int r  = it ? sr1 : sr0;
            int c4 = it ? sc1 : sc0;
            float4 v = ra[it];
            if (bn_mode) {
                float4 sc = *(const float4*)&bn[k0 + c4];
                float4 sh = *(const float4*)&bn[D + k0 + c4];
                v.x = fmaxf(v.x * sc.x + sh.x, 0.f);
                v.y = fmaxf(v.y * sc.y + sh.y, 0.f);
                v.z = fmaxf(v.z * sc.z + sh.z, 0.f);
                v.w = fmaxf(v.w * sc.w + sh.w, 0.f);
            }
            __half2 h0 = __floats2half2_rn(v.x, v.y);
            __half2 h1 = __floats2half2_rn(v.z, v.w);
            uint32_t* p = &shA[r * 12 + (c4 >> 1)];
            p[0] = *(uint32_t*)&h0;
            p[1] = *(uint32_t*)&h1;
        }
        asm volatile("cp.async.wait_group 0;" ::: "memory");
        __syncthreads();

        if (k0 + 16 < 128) {
            int kn = k0 + 16;
            int m = m0 + sr0;
            ra[0] = (m < N_NODES) ? *(const float4*)&A[(size_t)m * D + kn + sc0] : z4;
            m = m0 + sr1;
            ra[1] = (m < N_NODES) ? *(const float4*)&A[(size_t)m * D + kn + sc1] : z4;
        }

        {
            uint32_t bf[4][2];
#pragma unroll
            for (int j = 0; j < 4; j++) {
                int n = wn + j * 8 + grp;
                bf[j][0] = shB[n * 12 + tig];
                bf[j][1] = shB[n * 12 + tig + 4];
            }
#pragma unroll
            for (int i = 0; i < 4; i++) {
                int r0 = wm + i * 16 + grp;
                uint32_t af[4];
                af[0] = shA[r0 * 12 + tig];
                af[1] = shA[(r0 + 8) * 12 + tig];
                af[2] = shA[r0 * 12 + tig + 4];
                af[3] = shA[(r0 + 8) * 12 + tig + 4];
#pragma unroll
                for (int j = 0; j < 4; j++)
                    mma_f16(acc[i][j], af, bf[j]);
            }
        }
        __syncthreads();
    }

    float bs[4][2];
#pragma unroll
    for (int j = 0; j < 4; j++) {
        int col = wn + j * 8 + tig * 2;
        bs[j][0] = __ldg(&bias[col]);  bs[j][1] = __ldg(&bias[col + 1]);
    }
#pragma unroll
    for (int i = 0; i < 4; i++) {
        int rbase = m0 + wm + i * 16 + grp;
#pragma unroll
        for (int half = 0; half < 2; half++) {
            int m = rbase + half * 8;
            if (m >= N_NODES) continue;
#pragma unroll
            for (int j = 0; j < 4; j++) {
                int col = wn + j * 8 + tig * 2;
                float v0 = acc[i][j][half * 2 + 0] + bs[j][0];
                float v1 = acc[i][j][half * 2 + 1] + bs[j][1];
                __half2 h = __floats2half2_rn(v0, v1);
                *(uint32_t*)&g_hlh[(size_t)m * D + col] = *(uint32_t*)&h;
            }
        }
    }
}

// ---------------- gather: message + self term + fused BN stats ----------------
// Edge embeddings recomputed on the fly from smem-resident bond tables:
// emb[k][d] = sum_c bt[c][attr_c(k)][d]   (fp32, exact — no fp16 edge rounding)
__global__ __launch_bounds__(256)
void gather_kernel(int layer, const float* __restrict__ root,
                   const float* __restrict__ bt) {
    __shared__ float btab[3 * BVC * D];    // 15360 B
    __shared__ float shs[8 * 128];
    __shared__ float shq[8 * 128];
    float* out = g_outL + (size_t)layer * ND;
    int wid = threadIdx.x >> 5, lane = threadIdx.x & 31;
    int d4 = lane * 4;

    for (int i = threadIdx.x; i < 3 * BVC * D / 4; i += 256)
        ((float4*)btab)[i] = ((const float4*)bt)[i];
    __syncthreads();

    float4 rt = *(const float4*)&root[d4];
    float4 sum = make_float4(0.f, 0.f, 0.f, 0.f);
    float4 sq  = make_float4(0.f, 0.f, 0.f, 0.f);

    for (int n = blockIdx.x * 8 + wid; n < N_NODES; n += gridDim.x * 8) {
        int start = g_off[n];
        int end = (n < N_NODES - 1) ? g_off[n + 1] : N_EDGES;
        float inv = 1.f / g_deg[n];
        uint2 hp = *(const uint2*)&g_hlh[(size_t)n * D + d4];
        float2 h01 = __half22float2(*(__half2*)&hp.x);
        float2 h23 = __half22float2(*(__half2*)&hp.y);
        float4 acc;
        acc.x = fmaxf(h01.x + rt.x, 0.f) * inv;
        acc.y = fmaxf(h01.y + rt.y, 0.f) * inv;
        acc.z = fmaxf(h23.x + rt.z, 0.f) * inv;
        acc.w = fmaxf(h23.y + rt.w, 0.f) * inv;
        for (int k = start; k < end; k++) {
            int s = g_src[k];
            float nm = g_enorm[k];
            int pk = g_eattr[k];
            uint2 sp = *(const uint2*)&g_hlh[(size_t)s * D + d4];
            float2 s01 = __half22float2(*(__half2*)&sp.x);
            float2 s23 = __half22float2(*(__half2*)&sp.y);
            float4 t0 = *(const float4*)&btab[(pk & 15) * D + d4];
            float4 t1 = *(const float4*)&btab[(BVC + ((pk >> 4) & 15)) * D + d4];
            float4 t2 = *(const float4*)&btab[(2 * BVC + (pk >> 8)) * D + d4];
            float e0 = t0.x + t1.x + t2.x;
            float e1 = t0.y + t1.y + t2.y;
            float e2 = t0.z + t1.z + t2.z;
            float e3 = t0.w + t1.w + t2.w;
            acc.x += fmaxf(s01.x + e0, 0.f) * nm;
            acc.y += fmaxf(s01.y + e1, 0.f) * nm;
            acc.z += fmaxf(s23.x + e2, 0.f) * nm;
            acc.w += fmaxf(s23.y + e3, 0.f) * nm;
        }
        *(float4*)&out[(size_t)n * D + d4] = acc;
        sum.x += acc.x; sum.y += acc.y; sum.z += acc.z; sum.w += acc.w;
        sq.x += acc.x * acc.x; sq.y += acc.y * acc.y;
        sq.z += acc.z * acc.z; sq.w += acc.w * acc.w;
    }

    *(float4*)&shs[wid * 128 + d4] = sum;
    *(float4*)&shq[wid * 128 + d4] = sq;
    __syncthreads();
    if (threadIdx.x < 128) {
        float s = 0.f, q = 0.f;
#pragma unroll
        for (int w = 0; w < 8; w++) {
            s += shs[w * 128 + threadIdx.x];
            q += shq[w * 128 + threadIdx.x];
        }
        atomicAdd(&g_stats[threadIdx.x], s);
        atomicAdd(&g_stats[D + threadIdx.x], q);
    }
}

// ---------------- batch-norm params ----------------
__global__ void bn_kernel(int layer,
                          const float* __restrict__ gamma, const float* __restrict__ beta) {
    int d = threadIdx.x;
    float* bn = g_bnL + (size_t)layer * 2 * D;
    float mean = g_stats[d] * (1.f / N_NODES);
    float var = g_stats[D + d] * (1.f / N_NODES) - mean * mean;
    float sc = __ldg(&gamma[d]) * rsqrtf(var + BN_EPS);
    bn[d] = sc;
    bn[D + d] = __ldg(&beta[d]) - mean * sc;
}

// ---------------- final: total += sum_l bn_l(outL[l]) (relu for l < L-1) ----------------
__global__ void final_total_kernel(float* __restrict__ total) {
    int lane = threadIdx.x & 31;
    int warp = threadIdx.x >> 5;
    int d4 = lane * 4;
    float4 sc[NLAYER], sh[NLAYER];
#pragma unroll
    for (int l = 0; l < NLAYER; l++) {
        sc[l] = *(const float4*)&g_bnL[l * 2 * D + d4];
        sh[l] = *(const float4*)&g_bnL[l * 2 * D + D + d4];
    }
    for (int n = blockIdx.x * 8 + warp; n < N_NODES; n += gridDim.x * 8) {
        size_t idx = (size_t)n * D + d4;
        float4 t = *(const float4*)&total[idx];
#pragma unroll
        for (int l = 0; l < NLAYER; l++) {
            float4 v = *(const float4*)&g_outL[l * ND + idx];
            float w0 = v.x * sc[l].x + sh[l].x;
            float w1 = v.y * sc[l].y + sh[l].y;
            float w2 = v.z * sc[l].z + sh[l].z;
            float w3 = v.w * sc[l].w + sh[l].w;
            if (l < NLAYER - 1) {
                w0 = fmaxf(w0, 0.f); w1 = fmaxf(w1, 0.f);
                w2 = fmaxf(w2, 0.f); w3 = fmaxf(w3, 0.f);
            }
            t.x += w0; t.y += w1; t.z += w2; t.w += w3;
        }
        *(float4*)&total[idx] = t;
    }
}

// ---------------- launch ----------------
extern "C" void kernel_launch(void* const* d_in, const int* in_sizes, int n_in,
                              void* d_out, int out_size) {
    const int* x     = (const int*)d_in[0];
    const int* ei    = (const int*)d_in[1];
    const int* row   = ei;            // edge_index[0] : source j
    const int* col   = ei + N_EDGES;  // edge_index[1] : target i
    const int* ea    = (const int*)d_in[2];
    const float* at  = (const float*)d_in[3];
    const float* bt  = (const float*)d_in[4];
    const float* W   = (const float*)d_in[5];
    const float* b   = (const float*)d_in[6];
    const float* root  = (const float*)d_in[7];
    const float* gamma = (const float*)d_in[8];
    const float* beta  = (const float*)d_in[9];
    float* total = (float*)d_out;

    const int nscan = (N_NODES + 255) / 256;   // 782

    // Layer-0 GEMM is the 4th launch — that's the one ncu captures.
    encode_atoms_kernel<<<(N_NODES + 3) / 4, 128>>>(x, at, total);
    w_split_kernel<<<(NLAYER * 128 * 64 + 255) / 256, 256>>>(W);
    init_kernel<<<1024, 256>>>();
    gemm_tc_kernel<<<(N_NODES + 127) / 128, 256>>>(0, b);            // layer 0 GEMM
    deg_acc_kernel<<<1024, 256>>>(row);
    indeg_acc_kernel<<<1024, 256>>>(col);
    scan1_kernel<<<nscan, 256>>>();
    scan2_kernel<<<1, 1024>>>(nscan);
    scan3_kernel<<<nscan, 256>>>();
    fill_kernel<<<1024, 256>>>(row, col, ea);

    for (int l = 0; l < NLAYER; l++) {
        if (l > 0)
            gemm_tc_kernel<<<(N_NODES + 127) / 128, 256>>>(l, b + (size_t)l * D);
        gather_kernel<<<2048, 256>>>(l, root + (size_t)l * D, bt);
        bn_kernel<<<1, 128>>>(l, gamma + (size_t)l * D, beta + (size_t)l * D);
    }
    final_total_kernel<<<2048, 256>>>(total);
}

// round 15
// speedup vs baseline: 1.2250x; 1.2250x over previous
#include <cuda_runtime.h>
#include <cuda_fp16.h>
#include <cstdint>

#define N_NODES 200000
#define N_EDGES 400000
#define D 128
#define NLAYER 5
#define AVC 100
#define BVC 10
#define BN_EPS 1e-5f
#define ND ((size_t)N_NODES * D)

// ---------------- scratch (static device globals; no allocation) ----------------
__device__ __half g_hlh[ND];                    // linear output (fp16; gather-only consumer)
__device__ float g_outL[NLAYER * ND];           // per-layer aggregated output (pre-BN)
__device__ float g_h0[ND];                      // encoder output (layer-0 input)
__device__ __half g_edgeh[(size_t)N_EDGES * D]; // bond embeddings (CSR-permuted, fp16)
__device__ float g_deg[N_NODES];
__device__ float g_enorm[N_EDGES];              // norm per CSR slot
__device__ int   g_indeg[N_NODES];
__device__ int   g_off[N_NODES];                // CSR offsets (exclusive scan)
__device__ int   g_cursor[N_NODES];
__device__ int   g_bsum[1024];
__device__ int   g_src[N_EDGES];                // source node per CSR slot
__device__ int   g_eperm[N_EDGES];              // original edge id per CSR slot
__device__ float g_stats[2 * D];                // sum, sumsq
__device__ float g_bnL[NLAYER * 2 * D];         // per-layer scale, shift
// pre-converted W (fp16, k-pair packed): [layer][chunk(8)][n(128)][8 words]
__device__ __align__(16) uint32_t g_wsplit[(size_t)NLAYER * 8 * 128 * 8];

// ---------------- helpers ----------------
__device__ __forceinline__ void mma_f16(float* d, const uint32_t* a, const uint32_t* b) {
    asm volatile(
        "mma.sync.aligned.m16n8k16.row.col.f32.f16.f16.f32 "
        "{%0,%1,%2,%3}, {%4,%5,%6,%7}, {%8,%9}, {%0,%1,%2,%3};\n"
        : "+f"(d[0]), "+f"(d[1]), "+f"(d[2]), "+f"(d[3])
        : "r"(a[0]), "r"(a[1]), "r"(a[2]), "r"(a[3]), "r"(b[0]), "r"(b[1]));
}

__device__ __forceinline__ void cp_async16(uint32_t smem_addr, const void* gptr) {
    asm volatile("cp.async.ca.shared.global [%0], [%1], 16;"
                 :: "r"(smem_addr), "l"(gptr));
}

// ---------------- W fp16 precompute (all layers, once) ----------------
__global__ void w_split_kernel(const float* __restrict__ W) {
    int idx = blockIdx.x * blockDim.x + threadIdx.x;   // over NLAYER*128*64
    if (idx >= NLAYER * 128 * 64) return;
    int l = idx / 8192;
    int rem = idx - l * 8192;
    int n = rem >> 6;
    int kp = rem & 63;                 // k-pair index
    int k = kp * 2;
    float a = W[(size_t)l * 16384 + n * 128 + k];
    float b = W[(size_t)l * 16384 + n * 128 + k + 1];
    __half2 h = __floats2half2_rn(a, b);
    size_t dst = ((size_t)(l * 8 + (k >> 4)) * 128 + n) * 8 + (kp & 7);
    g_wsplit[dst] = *(uint32_t*)&h;
}

// ---------------- setup: degrees + CSR ----------------
__global__ void init_kernel() {
    int stride = gridDim.x * blockDim.x;
    for (int i = blockIdx.x * blockDim.x + threadIdx.x; i < N_NODES; i += stride) {
        g_deg[i] = 1.f;
        g_indeg[i] = 0;
    }
}

// fused: out-degree (row) and in-degree (col) in one pass over edge_index
__global__ void deg_acc_kernel(const int* __restrict__ row, const int* __restrict__ col) {
    for (int e = blockIdx.x * blockDim.x + threadIdx.x; e < N_EDGES;
         e += gridDim.x * blockDim.x) {
        atomicAdd(&g_deg[row[e]], 1.f);
        atomicAdd(&g_indeg[col[e]], 1);
    }
}

__global__ void scan1_kernel() {
    __shared__ int sh[256];
    int tid = threadIdx.x;
    int i = blockIdx.x * 256 + tid;
    int v = (i < N_NODES) ? g_indeg[i] : 0;
    sh[tid] = v;
    __syncthreads();
#pragma unroll
    for (int ofs = 1; ofs < 256; ofs <<= 1) {
        int t = (tid >= ofs) ? sh[tid - ofs] : 0;
        __syncthreads();
        sh[tid] += t;
        __syncthreads();
    }
    if (i < N_NODES) g_off[i] = sh[tid] - v;  // exclusive
    if (tid == 255) g_bsum[blockIdx.x] = sh[255];
}

__global__ void scan2_kernel(int nblk) {   // single block of 1024
    __shared__ int sh[1024];
    int tid = threadIdx.x;
    int v = (tid < nblk) ? g_bsum[tid] : 0;
    sh[tid] = v;
    __syncthreads();
#pragma unroll
    for (int ofs = 1; ofs < 1024; ofs <<= 1) {
        int t = (tid >= ofs) ? sh[tid - ofs] : 0;
        __syncthreads();
        sh[tid] += t;
        __syncthreads();
    }
    if (tid < nblk) g_bsum[tid] = sh[tid] - v;  // exclusive
}

__global__ void scan3_kernel() {
    int i = blockIdx.x * 256 + threadIdx.x;
    if (i < N_NODES) {
        int o = g_off[i] + g_bsum[blockIdx.x];
        g_off[i] = o;
        g_cursor[i] = o;
    }
}

__global__ void fill_kernel(const int* __restrict__ row, const int* __restrict__ col) {
    for (int e = blockIdx.x * blockDim.x + threadIdx.x; e < N_EDGES;
         e += gridDim.x * blockDim.x) {
        int r = row[e], c = col[e];
        int pos = atomicAdd(&g_cursor[c], 1);
        g_src[pos] = r;
        g_eperm[pos] = e;
        g_enorm[pos] = rsqrtf(g_deg[r]) * rsqrtf(g_deg[c]);
    }
}

// ---------------- encoders ----------------
__global__ void encode_atoms_kernel(const int* __restrict__ x,
                                    const float* __restrict__ at,
                                    float* __restrict__ total) {
    int n = blockIdx.x * 4 + (threadIdx.x >> 5);
    if (n >= N_NODES) return;
    int d4 = (threadIdx.x & 31) * 4;
    float4 s = make_float4(0.f, 0.f, 0.f, 0.f);
#pragma unroll
    for (int c = 0; c < 9; c++) {
        int idx = __ldg(&x[n * 9 + c]);
        float4 v = *(const float4*)&at[((size_t)c * AVC + idx) * D + d4];
        s.x += v.x; s.y += v.y; s.z += v.z; s.w += v.w;
    }
    *(float4*)&g_h0[(size_t)n * D + d4] = s;
    *(float4*)&total[(size_t)n * D + d4] = s;
}

// bond embeddings written in CSR-permuted order as fp16
__global__ void encode_bonds_kernel(const int* __restrict__ ea,
                                    const float* __restrict__ bt) {
    int pos = blockIdx.x * 4 + (threadIdx.x >> 5);
    if (pos >= N_EDGES) return;
    int e = g_eperm[pos];
    int d4 = (threadIdx.x & 31) * 4;
    float4 s = make_float4(0.f, 0.f, 0.f, 0.f);
#pragma unroll
    for (int c = 0; c < 3; c++) {
        int idx = __ldg(&ea[e * 3 + c]);
        float4 v = *(const float4*)&bt[((size_t)c * BVC + idx) * D + d4];
        s.x += v.x; s.y += v.y; s.z += v.z; s.w += v.w;
    }
    __half2 h01 = __floats2half2_rn(s.x, s.y);
    __half2 h23 = __floats2half2_rn(s.z, s.w);
    uint2 p;
    p.x = *(uint32_t*)&h01;
    p.y = *(uint32_t*)&h23;
    *(uint2*)&g_edgeh[(size_t)pos * D + d4] = p;
}

// ---------------- GEMM (fp16 MMA m16n8k16, fp32 accum, cp.async B) ----------------
// layer==0: A = g_h0 raw. layer>0: A = relu(bn(g_outL[layer-1])) on load (fp16-rounded).
// Writes g_hlh (fp16). Block 0 zeroes g_stats for the following gather.
__global__ __launch_bounds__(256, 2)
void gemm_tc_kernel(int layer, const float* __restrict__ bias) {
    __shared__ __align__(16) uint32_t shA[128 * 12];  // [row][8 k-pair words], stride 12
    __shared__ __align__(16) uint32_t shB[128 * 12];  // [n][8 k-pair words], stride 12

    const float* A = (layer == 0) ? g_h0 : (g_outL + (size_t)(layer - 1) * ND);
    const float* bn = g_bnL + (size_t)(layer > 0 ? layer - 1 : 0) * 2 * D;
    const int bn_mode = (layer > 0);
    const uint4* wbase = (const uint4*)&g_wsplit[(size_t)layer * 8 * 128 * 8];

    const int tid = threadIdx.x;
    if (blockIdx.x == 0 && tid < 2 * D) g_stats[tid] = 0.f;

    const int m0 = blockIdx.x * 128;
    const int lane = tid & 31, grp = lane >> 2, tig = lane & 3;
    const int wid = tid >> 5;
    const int wm = (wid & 1) * 64;
    const int wn = (wid >> 1) * 32;

    const int sr0 = tid >> 2,         sc0 = (tid & 3) * 4;
    const int sr1 = (tid + 256) >> 2, sc1 = ((tid + 256) & 3) * 4;

    const uint32_t bdst = (uint32_t)__cvta_generic_to_shared(
        &shB[(tid >> 1) * 12 + (tid & 1) * 4]);

    float acc[4][4][4];
#pragma unroll
    for (int i = 0; i < 4; i++)
#pragma unroll
        for (int j = 0; j < 4; j++)
#pragma unroll
            for (int k = 0; k < 4; k++) acc[i][j][k] = 0.f;

    const float4 z4 = make_float4(0.f, 0.f, 0.f, 0.f);
    float4 ra[2];
    {
        int m = m0 + sr0;
        ra[0] = (m < N_NODES) ? *(const float4*)&A[(size_t)m * D + sc0] : z4;
        m = m0 + sr1;
        ra[1] = (m < N_NODES) ? *(const float4*)&A[(size_t)m * D + sc1] : z4;
    }

    for (int k0 = 0; k0 < 128; k0 += 16) {
        cp_async16(bdst, wbase + (size_t)(k0 >> 4) * 256 + tid);
        asm volatile("cp.async.commit_group;");

#pragma unroll
        for (int it = 0; it < 2; it++) {
            int r  = it ? sr1 : sr0;
            int c4 = it ? sc1 : sc0;
            float4 v = ra[it];
            if (bn_mode) {
                float4 sc = *(const float4*)&bn[k0 + c4];
                float4 sh = *(const float4*)&bn[D + k0 + c4];
                v.x = fmaxf(v.x * sc.x + sh.x, 0.f);
                v.y = fmaxf(v.y * sc.y + sh.y, 0.f);
                v.z = fmaxf(v.z * sc.z + sh.z, 0.f);
                v.w = fmaxf(v.w * sc.w + sh.w, 0.f);
            }
            __half2 h0 = __floats2half2_rn(v.x, v.y);
            __half2 h1 = __floats2half2_rn(v.z, v.w);
            uint32_t* p = &shA[r * 12 + (c4 >> 1)];
            p[0] = *(uint32_t*)&h0;
            p[1] = *(uint32_t*)&h1;
        }
        asm volatile("cp.async.wait_group 0;" ::: "memory");
        __syncthreads();

        if (k0 + 16 < 128) {
            int kn = k0 + 16;
            int m = m0 + sr0;
            ra[0] = (m < N_NODES) ? *(const float4*)&A[(size_t)m * D + kn + sc0] : z4;
            m = m0 + sr1;
            ra[1] = (m < N_NODES) ? *(const float4*)&A[(size_t)m * D + kn + sc1] : z4;
        }

        {
            uint32_t bf[4][2];
#pragma unroll
            for (int j = 0; j < 4; j++) {
                int n = wn + j * 8 + grp;
                bf[j][0] = shB[n * 12 + tig];
                bf[j][1] = shB[n * 12 + tig + 4];
            }
#pragma unroll
            for (int i = 0; i < 4; i++) {
                int r0 = wm + i * 16 + grp;
                uint32_t af[4];
                af[0] = shA[r0 * 12 + tig];
                af[1] = shA[(r0 + 8) * 12 + tig];
                af[2] = shA[r0 * 12 + tig + 4];
                af[3] = shA[(r0 + 8) * 12 + tig + 4];
#pragma unroll
                for (int j = 0; j < 4; j++)
                    mma_f16(acc[i][j], af, bf[j]);
            }
        }
        __syncthreads();
    }

    float bs[4][2];
#pragma unroll
    for (int j = 0; j < 4; j++) {
        int col = wn + j * 8 + tig * 2;
        bs[j][0] = __ldg(&bias[col]);  bs[j][1] = __ldg(&bias[col + 1]);
    }
#pragma unroll
    for (int i = 0; i < 4; i++) {
        int rbase = m0 + wm + i * 16 + grp;
#pragma unroll
        for (int half = 0; half < 2; half++) {
            int m = rbase + half * 8;
            if (m >= N_NODES) continue;
#pragma unroll
            for (int j = 0; j < 4; j++) {
                int col = wn + j * 8 + tig * 2;
                float v0 = acc[i][j][half * 2 + 0] + bs[j][0];
                float v1 = acc[i][j][half * 2 + 1] + bs[j][1];
                __half2 h = __floats2half2_rn(v0, v1);
                *(uint32_t*)&g_hlh[(size_t)m * D + col] = *(uint32_t*)&h;
            }
        }
    }
}

// ---------------- gather message + self term + fused BN stats ----------------
__global__ __launch_bounds__(256)
void gather_kernel(int layer, const float* __restrict__ root) {
    __shared__ float shs[8 * 128];
    __shared__ float shq[8 * 128];
    float* out = g_outL + (size_t)layer * ND;
    int wid = threadIdx.x >> 5, lane = threadIdx.x & 31;
    int d4 = lane * 4;
    float4 rt = *(const float4*)&root[d4];
    float4 sum = make_float4(0.f, 0.f, 0.f, 0.f);
    float4 sq  = make_float4(0.f, 0.f, 0.f, 0.f);

    for (int n = blockIdx.x * 8 + wid; n < N_NODES; n += gridDim.x * 8) {
        int start = g_off[n];
        int end = (n < N_NODES - 1) ? g_off[n + 1] : N_EDGES;
        float inv = 1.f / g_deg[n];
        uint2 hp = *(const uint2*)&g_hlh[(size_t)n * D + d4];
        float2 h01 = __half22float2(*(__half2*)&hp.x);
        float2 h23 = __half22float2(*(__half2*)&hp.y);
        float4 acc;
        acc.x = fmaxf(h01.x + rt.x, 0.f) * inv;
        acc.y = fmaxf(h01.y + rt.y, 0.f) * inv;
        acc.z = fmaxf(h23.x + rt.z, 0.f) * inv;
        acc.w = fmaxf(h23.y + rt.w, 0.f) * inv;
        for (int k = start; k < end; k++) {
            int s = g_src[k];
            float nm = g_enorm[k];
            uint2 sp = *(const uint2*)&g_hlh[(size_t)s * D + d4];
            float2 s01 = __half22float2(*(__half2*)&sp.x);
            float2 s23 = __half22float2(*(__half2*)&sp.y);
            uint2 ep = *(const uint2*)&g_edgeh[(size_t)k * D + d4];
            float2 e01 = __half22float2(*(__half2*)&ep.x);
            float2 e23 = __half22float2(*(__half2*)&ep.y);
            acc.x += fmaxf(s01.x + e01.x, 0.f) * nm;
            acc.y += fmaxf(s01.y + e01.y, 0.f) * nm;
            acc.z += fmaxf(s23.x + e23.x, 0.f) * nm;
            acc.w += fmaxf(s23.y + e23.y, 0.f) * nm;
        }
        *(float4*)&out[(size_t)n * D + d4] = acc;
        sum.x += acc.x; sum.y += acc.y; sum.z += acc.z; sum.w += acc.w;
        sq.x += acc.x * acc.x; sq.y += acc.y * acc.y;
        sq.z += acc.z * acc.z; sq.w += acc.w * acc.w;
    }

    *(float4*)&shs[wid * 128 + d4] = sum;
    *(float4*)&shq[wid * 128 + d4] = sq;
    __syncthreads();
    if (threadIdx.x < 128) {
        float s = 0.f, q = 0.f;
#pragma unroll
        for (int w = 0; w < 8; w++) {
            s += shs[w * 128 + threadIdx.x];
            q += shq[w * 128 + threadIdx.x];
        }
        atomicAdd(&g_stats[threadIdx.x], s);
        atomicAdd(&g_stats[D + threadIdx.x], q);
    }
}

// ---------------- batch-norm params ----------------
__global__ void bn_kernel(int layer,
                          const float* __restrict__ gamma, const float* __restrict__ beta) {
    int d = threadIdx.x;
    float* bn = g_bnL + (size_t)layer * 2 * D;
    float mean = g_stats[d] * (1.f / N_NODES);
    float var = g_stats[D + d] * (1.f / N_NODES) - mean * mean;
    float sc = __ldg(&gamma[d]) * rsqrtf(var + BN_EPS);
    bn[d] = sc;
    bn[D + d] = __ldg(&beta[d]) - mean * sc;
}

// ---------------- final: total += sum_l bn_l(outL[l]) (relu for l < L-1) ----------------
__global__ void final_total_kernel(float* __restrict__ total) {
    int lane = threadIdx.x & 31;
    int warp = threadIdx.x >> 5;
    int d4 = lane * 4;
    float4 sc[NLAYER], sh[NLAYER];
#pragma unroll
    for (int l = 0; l < NLAYER; l++) {
        sc[l] = *(const float4*)&g_bnL[l * 2 * D + d4];
        sh[l] = *(const float4*)&g_bnL[l * 2 * D + D + d4];
    }
    for (int n = blockIdx.x * 8 + warp; n < N_NODES; n += gridDim.x * 8) {
        size_t idx = (size_t)n * D + d4;
        float4 t = *(const float4*)&total[idx];
#pragma unroll
        for (int l = 0; l < NLAYER; l++) {
            float4 v = *(const float4*)&g_outL[l * ND + idx];
            float w0 = v.x * sc[l].x + sh[l].x;
            float w1 = v.y * sc[l].y + sh[l].y;
            float w2 = v.z * sc[l].z + sh[l].z;
            float w3 = v.w * sc[l].w + sh[l].w;
            if (l < NLAYER - 1) {
                w0 = fmaxf(w0, 0.f); w1 = fmaxf(w1, 0.f);
                w2 = fmaxf(w2, 0.f); w3 = fmaxf(w3, 0.f);
            }
            t.x += w0; t.y += w1; t.z += w2; t.w += w3;
        }
        *(float4*)&total[idx] = t;
    }
}

// ---------------- launch ----------------
extern "C" void kernel_launch(void* const* d_in, const int* in_sizes, int n_in,
                              void* d_out, int out_size) {
    const int* x     = (const int*)d_in[0];
    const int* ei    = (const int*)d_in[1];
    const int* row   = ei;            // edge_index[0] : source j
    const int* col   = ei + N_EDGES;  // edge_index[1] : target i
    const int* ea    = (const int*)d_in[2];
    const float* at  = (const float*)d_in[3];
    const float* bt  = (const float*)d_in[4];
    const float* W   = (const float*)d_in[5];
    const float* b   = (const float*)d_in[6];
    const float* root  = (const float*)d_in[7];
    const float* gamma = (const float*)d_in[8];
    const float* beta  = (const float*)d_in[9];
    float* total = (float*)d_out;

    const int nscan = (N_NODES + 255) / 256;   // 782

    // Layer-0 GEMM is the 4th launch — that's the one ncu captures.
    encode_atoms_kernel<<<(N_NODES + 3) / 4, 128>>>(x, at, total);
    w_split_kernel<<<(NLAYER * 128 * 64 + 255) / 256, 256>>>(W);
    init_kernel<<<1024, 256>>>();
    gemm_tc_kernel<<<(N_NODES + 127) / 128, 256>>>(0, b);            // layer 0 GEMM
    deg_acc_kernel<<<1024, 256>>>(row, col);
    scan1_kernel<<<nscan, 256>>>();
    scan2_kernel<<<1, 1024>>>(nscan);
    scan3_kernel<<<nscan, 256>>>();
    fill_kernel<<<1024, 256>>>(row, col);
    encode_bonds_kernel<<<(N_EDGES + 3) / 4, 128>>>(ea, bt);

    for (int l = 0; l < NLAYER; l++) {
        if (l > 0)
            gemm_tc_kernel<<<(N_NODES + 127) / 128, 256>>>(l, b + (size_t)l * D);
        gather_kernel<<<2048, 256>>>(l, root + (size_t)l * D);
        bn_kernel<<<1, 128>>>(l, gamma + (size_t)l * D, beta + (size_t)l * D);
    }
    final_total_kernel<<<2048, 256>>>(total);
}